// round 13
// baseline (speedup 1.0000x reference)
#include <cuda_runtime.h>

#define NQ      8
#define KCODES  1024
#define DIM     64
#define TOKENS  65536
#define TILE    128
#define CTA     128
#define WARPS   4
#define TPW     16
#define ROWF    68          // padded row stride (floats): bank-conflict-free
#define CB      3           // candidate buffer per token-slot per lane

typedef unsigned long long u64;
typedef unsigned int u32;

__device__ float g_csq[NQ * KCODES];
__device__ u32   g_maxcsq[NQ];                 // float bits of max csq per stage
__device__ float g_cbtf[NQ * KCODES * DIM];    // tf32-truncated codebook

__device__ __forceinline__ u64 make_key(float s, u32 idx) {
    u32 b = __float_as_uint(s);
    u32 u = b ^ (u32)(((int)b >> 31) | 0x80000000);
    return ((u64)u << 32) | idx;
}
__device__ __forceinline__ u32 to_tf32(float f) {
    u32 r;
    asm("cvt.rna.tf32.f32 %0, %1;" : "=r"(r) : "f"(f));
    return r;
}
__device__ __forceinline__ u32 smem_u32(const void* p) {
    u32 a;
    asm("{ .reg .u64 t; cvta.to.shared.u64 t, %1; cvt.u32.u64 %0, t; }"
        : "=r"(a) : "l"(p));
    return a;
}
__device__ __forceinline__ void cp_async16(u32 dst, const void* src) {
    asm volatile("cp.async.cg.shared.global [%0], [%1], 16;"
                 :: "r"(dst), "l"(src) : "memory");
}
__device__ __forceinline__ void mma8(float& d0, float& d1, float& d2, float& d3,
                                     u32 a0, u32 a1, u32 a2, u32 a3,
                                     u32 b0, u32 b1) {
    asm("mma.sync.aligned.m16n8k8.row.col.f32.tf32.tf32.f32 "
        "{%0,%1,%2,%3},{%4,%5,%6,%7},{%8,%9},{%0,%1,%2,%3};"
        : "+f"(d0), "+f"(d1), "+f"(d2), "+f"(d3)
        : "r"(a0), "r"(a1), "r"(a2), "r"(a3), "r"(b0), "r"(b1));
}

// prep: exact csq (sequential fadd(fmul)), per-stage max csq, tf32 codebook copy
__global__ void prep_kernel(const float* __restrict__ cb) {
    int r = blockIdx.x * blockDim.x + threadIdx.x;    // 0..8191
    const float* row = cb + (size_t)r * DIM;
    float s = 0.f;
#pragma unroll
    for (int d = 0; d < DIM; d++)
        s = __fadd_rn(s, __fmul_rn(row[d], row[d]));
    g_csq[r] = s;
    atomicMax(&g_maxcsq[r >> 10], __float_as_uint(s));  // s > 0: bit-monotone
#pragma unroll
    for (int d = 0; d < DIM; d++)
        g_cbtf[r * DIM + d] = __uint_as_float(to_tf32(row[d]));
}

// exact rescore: sequential d-ascending fma chain (bit-identical to reference)
__device__ __forceinline__ u64 rescore(const float* __restrict__ cb, int q,
                                       u32 code, const float* myrow, float rs) {
    const float* crow = cb + ((size_t)q * KCODES + code) * DIM;
    float dot = 0.f;
#pragma unroll
    for (int d = 0; d < DIM; d++)
        dot = __fmaf_rn(myrow[d], crow[d], dot);
    float s = __fadd_rn(__fsub_rn(rs, __fmul_rn(2.0f, dot)),
                        g_csq[q * KCODES + code]);
    return make_key(s, code);
}

__global__ void __launch_bounds__(CTA)
rvq_kernel(const float* __restrict__ x,
           const float* __restrict__ cb,
           float* __restrict__ out) {
    extern __shared__ float sm[];
    float* tile = sm;                        // [TILE][ROWF] tf32 bits as f32
    float* scq  = sm + TILE * ROWF;          // [TILE]
    float* myr_ = scq + TILE;                // [WARPS][TPW][ROWF]

    const int tid  = threadIdx.x;
    const int wid  = tid >> 5;
    const int lane = tid & 31;
    const int g    = lane >> 2;              // row group 0..7
    const int t    = lane & 3;               // col-in-group
    const int tokenBase = blockIdx.x * (WARPS * TPW) + wid * TPW;

    float* myr = myr_ + wid * TPW * ROWF;    // token-major rows
    const u32 tile_b = smem_u32(tile);

    // init: lane tok<16 owns token tok; residual=x, exact rsq
    float rs = 0.f;
    if (lane < TPW) {
        const float4* xr = reinterpret_cast<const float4*>(
            x + (size_t)(tokenBase + lane) * DIM);
        float* mrow = myr + lane * ROWF;
#pragma unroll
        for (int i = 0; i < DIM / 4; i++) {
            float4 v = xr[i];
            mrow[4 * i]     = v.x;  rs = __fadd_rn(rs, __fmul_rn(v.x, v.x));
            mrow[4 * i + 1] = v.y;  rs = __fadd_rn(rs, __fmul_rn(v.y, v.y));
            mrow[4 * i + 2] = v.z;  rs = __fadd_rn(rs, __fmul_rn(v.z, v.z));
            mrow[4 * i + 3] = v.w;  rs = __fadd_rn(rs, __fmul_rn(v.w, v.w));
        }
    }
    __syncwarp();
    float rs0 = __shfl_sync(0xffffffffu, rs, g);
    float rs1 = __shfl_sync(0xffffffffu, rs, g + 8);

#pragma unroll 1
    for (int q = 0; q < NQ; q++) {
        // A fragments for this stage: 8 ksteps x 4 regs (tf32)
        u32 Ar[8][4];
#pragma unroll
        for (int kk = 0; kk < 8; kk++) {
            Ar[kk][0] = to_tf32(myr[g * ROWF + 8 * kk + t]);
            Ar[kk][1] = to_tf32(myr[(g + 8) * ROWF + 8 * kk + t]);
            Ar[kk][2] = to_tf32(myr[g * ROWF + 8 * kk + t + 4]);
            Ar[kk][3] = to_tf32(myr[(g + 8) * ROWF + 8 * kk + t + 4]);
        }

        const float maxcsq = __uint_as_float(g_maxcsq[q]);
        const float C9 = 1.0f / 512.0f;
        const float bmax0 = (rs0 + maxcsq) * C9;
        const float bmax1 = (rs1 + maxcsq) * C9;

        float min0 = 3.4e38f, min1 = 3.4e38f;
        float marg0[CB], marg1[CB];
        u32   cidx0[CB], cidx1[CB];
        int   cnt0 = 0, cnt1 = 0;

#pragma unroll 1
        for (int c = 0; c < KCODES / TILE; c++) {
            __syncthreads();
            {   // load tf32 tile (padded rows) + csq tile
                const float* src = g_cbtf
                    + ((size_t)q * KCODES + c * TILE + tid) * DIM;
#pragma unroll
                for (int i = 0; i < DIM / 4; i++)
                    cp_async16(tile_b + (u32)((tid * ROWF + 4 * i) * 4),
                               src + 4 * i);
                scq[tid] = g_csq[q * KCODES + c * TILE + tid];
                asm volatile("cp.async.commit_group;" ::: "memory");
                asm volatile("cp.async.wait_group 0;" ::: "memory");
            }
            __syncthreads();

#pragma unroll 1
            for (int nb = 0; nb < TILE / 8; nb++) {
                float d0 = 0.f, d1 = 0.f, d2 = 0.f, d3 = 0.f;
                const float* brow = tile + (nb * 8 + g) * ROWF;
#pragma unroll
                for (int kk = 0; kk < 8; kk++) {
                    u32 b0 = __float_as_uint(brow[8 * kk + t]);
                    u32 b1 = __float_as_uint(brow[8 * kk + t + 4]);
                    mma8(d0, d1, d2, d3,
                         Ar[kk][0], Ar[kk][1], Ar[kk][2], Ar[kk][3], b0, b1);
                }
                // approx scores; codes k0,k0+1 (cols 2t,2t+1)
                u32 k0 = (u32)(c * TILE + nb * 8 + 2 * t);
                float cs0 = scq[nb * 8 + 2 * t];
                float cs1 = scq[nb * 8 + 2 * t + 1];

                float s00 = fmaf(-2.f, d0, rs0) + cs0;
                float s01 = fmaf(-2.f, d1, rs0) + cs1;
                float s10 = fmaf(-2.f, d2, rs1) + cs0;
                float s11 = fmaf(-2.f, d3, rs1) + cs1;

                float m;
                m = s00 - (rs0 + cs0) * C9;
                if (m <= min0 + bmax0) {
                    if (cnt0 < CB) { marg0[cnt0] = m; cidx0[cnt0] = k0; }
                    cnt0++;
                }
                if (s00 < min0) min0 = s00;
                m = s01 - (rs0 + cs1) * C9;
                if (m <= min0 + bmax0) {
                    if (cnt0 < CB) { marg0[cnt0] = m; cidx0[cnt0] = k0 + 1; }
                    cnt0++;
                }
                if (s01 < min0) min0 = s01;
                m = s10 - (rs1 + cs0) * C9;
                if (m <= min1 + bmax1) {
                    if (cnt1 < CB) { marg1[cnt1] = m; cidx1[cnt1] = k0; }
                    cnt1++;
                }
                if (s10 < min1) min1 = s10;
                m = s11 - (rs1 + cs1) * C9;
                if (m <= min1 + bmax1) {
                    if (cnt1 < CB) { marg1[cnt1] = m; cidx1[cnt1] = k0 + 1; }
                    cnt1++;
                }
                if (s11 < min1) min1 = s11;
            }
        }

        // merge approx mins + overflow flags across the 4 lanes of each group
        min0 = fminf(min0, __shfl_xor_sync(0xffffffffu, min0, 1));
        min0 = fminf(min0, __shfl_xor_sync(0xffffffffu, min0, 2));
        min1 = fminf(min1, __shfl_xor_sync(0xffffffffu, min1, 1));
        min1 = fminf(min1, __shfl_xor_sync(0xffffffffu, min1, 2));
        u32 ovf0 = (cnt0 > CB) ? 1u : 0u;
        u32 ovf1 = (cnt1 > CB) ? 1u : 0u;
        ovf0 |= __shfl_xor_sync(0xffffffffu, ovf0, 1);
        ovf0 |= __shfl_xor_sync(0xffffffffu, ovf0, 2);
        ovf1 |= __shfl_xor_sync(0xffffffffu, ovf1, 1);
        ovf1 |= __shfl_xor_sync(0xffffffffu, ovf1, 2);

        // exact rescore of surviving candidates
        u64 key0 = 0xFFFFFFFFFFFFFFFFull, key1 = 0xFFFFFFFFFFFFFFFFull;
        int n0 = (cnt0 < CB) ? cnt0 : CB;
        int n1 = (cnt1 < CB) ? cnt1 : CB;
        for (int i = 0; i < n0; i++)
            if (marg0[i] <= min0 + bmax0) {
                u64 k = rescore(cb, q, cidx0[i], myr + g * ROWF, rs0);
                if (k < key0) key0 = k;
            }
        for (int i = 0; i < n1; i++)
            if (marg1[i] <= min1 + bmax1) {
                u64 k = rescore(cb, q, cidx1[i], myr + (g + 8) * ROWF, rs1);
                if (k < key1) key1 = k;
            }
        {
            u64 o;
            o = __shfl_xor_sync(0xffffffffu, key0, 1); if (o < key0) key0 = o;
            o = __shfl_xor_sync(0xffffffffu, key0, 2); if (o < key0) key0 = o;
            o = __shfl_xor_sync(0xffffffffu, key1, 1); if (o < key1) key1 = o;
            o = __shfl_xor_sync(0xffffffffu, key1, 2); if (o < key1) key1 = o;
        }
        if (ovf0) key0 = 0ull;                 // sentinel: full exact scan
        if (ovf1) key1 = 0ull;

        // route winner key to owner lane (lane tok<16 owns token tok)
        int src = (lane & 7) * 4;
        u64 kw0 = __shfl_sync(0xffffffffu, key0, src);
        u64 kw1 = __shfl_sync(0xffffffffu, key1, src);
        u64 kw  = (lane < 8) ? kw0 : kw1;

        // residual update + fused exact rsq (owner lane)
        rs = 0.f;
        if (lane < TPW) {
            float* mrow = myr + lane * ROWF;
            u32 bk;
            if (kw == 0ull) {                  // rare fallback: full exact scan
                u64 kbest = 0xFFFFFFFFFFFFFFFFull;
                float rloc = rs0;              // not valid here; recompute below
                (void)rloc;
                // recompute exact rsq-independent scan using stored row
                float rsq_tok = 0.f;
#pragma unroll
                for (int d = 0; d < DIM; d++)
                    rsq_tok = __fadd_rn(rsq_tok,
                                        __fmul_rn(mrow[d], mrow[d]));
                for (int k = 0; k < KCODES; k++) {
                    u64 kk2 = rescore(cb, q, (u32)k, mrow, rsq_tok);
                    if (kk2 < kbest) kbest = kk2;
                }
                bk = (u32)(kbest & 0xFFFFu);
            } else {
                bk = (u32)(kw & 0xFFFFu);
            }
            const float4* crow = reinterpret_cast<const float4*>(
                cb + ((size_t)q * KCODES + bk) * DIM);
#pragma unroll
            for (int i = 0; i < DIM / 4; i++) {
                float4 v = crow[i];
                float r0 = __fsub_rn(mrow[4 * i],     v.x);
                float r1 = __fsub_rn(mrow[4 * i + 1], v.y);
                float r2 = __fsub_rn(mrow[4 * i + 2], v.z);
                float r3 = __fsub_rn(mrow[4 * i + 3], v.w);
                mrow[4 * i]     = r0;
                mrow[4 * i + 1] = r1;
                mrow[4 * i + 2] = r2;
                mrow[4 * i + 3] = r3;
                rs = __fadd_rn(rs, __fmul_rn(r0, r0));
                rs = __fadd_rn(rs, __fmul_rn(r1, r1));
                rs = __fadd_rn(rs, __fmul_rn(r2, r2));
                rs = __fadd_rn(rs, __fmul_rn(r3, r3));
            }
        }
        __syncwarp();
        rs0 = __shfl_sync(0xffffffffu, rs, g);
        rs1 = __shfl_sync(0xffffffffu, rs, g + 8);
    }

    // out = x - residual_final (exact fsub)
    if (lane < TPW) {
        const float4* xr = reinterpret_cast<const float4*>(
            x + (size_t)(tokenBase + lane) * DIM);
        float4* orw = reinterpret_cast<float4*>(
            out + (size_t)(tokenBase + lane) * DIM);
        const float* mrow = myr + lane * ROWF;
#pragma unroll
        for (int i = 0; i < DIM / 4; i++) {
            float4 v = xr[i];
            v.x = __fsub_rn(v.x, mrow[4 * i]);
            v.y = __fsub_rn(v.y, mrow[4 * i + 1]);
            v.z = __fsub_rn(v.z, mrow[4 * i + 2]);
            v.w = __fsub_rn(v.w, mrow[4 * i + 3]);
            orw[i] = v;
        }
    }
}

extern "C" void kernel_launch(void* const* d_in, const int* in_sizes, int n_in,
                              void* d_out, int out_size) {
    const float* x;
    const float* cb;
    if (in_sizes[0] == NQ * KCODES * DIM) {
        cb = (const float*)d_in[0];
        x  = (const float*)d_in[1];
    } else {
        x  = (const float*)d_in[0];
        cb = (const float*)d_in[1];
    }
    float* out = (float*)d_out;

    const int smem_bytes = (TILE * ROWF + TILE + WARPS * TPW * ROWF)
                           * (int)sizeof(float);
    cudaFuncSetAttribute(rvq_kernel,
                         cudaFuncAttributeMaxDynamicSharedMemorySize, smem_bytes);

    prep_kernel<<<(NQ * KCODES) / 128, 128>>>(cb);
    rvq_kernel<<<TOKENS / (WARPS * TPW), CTA, smem_bytes>>>(x, cb, out);
}

// round 14
// speedup vs baseline: 9.7920x; 9.7920x over previous
#include <cuda_runtime.h>

#define NQ      8
#define KCODES  1024
#define DIM     64
#define TOKENS  65536
#define TILE    128
#define CTA     128
#define WARPS   4
#define TPW     16
#define ROWF    68          // padded row stride (floats), 272B = 16B-aligned

typedef unsigned long long u64;
typedef unsigned int u32;

__device__ float g_csq[NQ * KCODES];
__device__ u32   g_maxcsq[NQ];                 // float bits of max csq per stage
__device__ float g_cbtf[NQ * KCODES * DIM];    // tf32-rounded codebook

__device__ __forceinline__ u64 make_key(float s, u32 idx) {
    u32 b = __float_as_uint(s);
    u32 u = b ^ (u32)(((int)b >> 31) | 0x80000000);
    return ((u64)u << 32) | idx;
}
__device__ __forceinline__ u32 to_tf32(float f) {
    u32 r;
    asm("cvt.rna.tf32.f32 %0, %1;" : "=r"(r) : "f"(f));
    return r;
}
__device__ __forceinline__ u32 smem_u32(const void* p) {
    u32 a;
    asm("{ .reg .u64 t; cvta.to.shared.u64 t, %1; cvt.u32.u64 %0, t; }"
        : "=r"(a) : "l"(p));
    return a;
}
__device__ __forceinline__ void cp_async16(u32 dst, const void* src) {
    asm volatile("cp.async.cg.shared.global [%0], [%1], 16;"
                 :: "r"(dst), "l"(src) : "memory");
}
__device__ __forceinline__ void mma8(float& d0, float& d1, float& d2, float& d3,
                                     u32 a0, u32 a1, u32 a2, u32 a3,
                                     u32 b0, u32 b1) {
    asm("mma.sync.aligned.m16n8k8.row.col.f32.tf32.tf32.f32 "
        "{%0,%1,%2,%3},{%4,%5,%6,%7},{%8,%9},{%0,%1,%2,%3};"
        : "+f"(d0), "+f"(d1), "+f"(d2), "+f"(d3)
        : "r"(a0), "r"(a1), "r"(a2), "r"(a3), "r"(b0), "r"(b1));
}

__global__ void prep_kernel(const float* __restrict__ cb) {
    int r = blockIdx.x * blockDim.x + threadIdx.x;    // 0..8191
    const float* row = cb + (size_t)r * DIM;
    float s = 0.f;
#pragma unroll
    for (int d = 0; d < DIM; d++)
        s = __fadd_rn(s, __fmul_rn(row[d], row[d]));
    g_csq[r] = s;
    atomicMax(&g_maxcsq[r >> 10], __float_as_uint(s));  // s>0: bit-monotone
#pragma unroll
    for (int d = 0; d < DIM; d++)
        g_cbtf[r * DIM + d] = __uint_as_float(to_tf32(row[d]));
}

// exact rescore: sequential d-ascending fp32 fma chain (reference recipe)
__device__ __forceinline__ u64 rescore(const float* __restrict__ crow,
                                       const float* __restrict__ mrow,
                                       float rs, float cs, u32 code) {
    float dot = 0.f;
#pragma unroll 1
    for (int i = 0; i < DIM / 4; i++) {
        float4 cv = reinterpret_cast<const float4*>(crow)[i];
        float4 rv = reinterpret_cast<const float4*>(mrow)[i];
        dot = __fmaf_rn(rv.x, cv.x, dot);
        dot = __fmaf_rn(rv.y, cv.y, dot);
        dot = __fmaf_rn(rv.z, cv.z, dot);
        dot = __fmaf_rn(rv.w, cv.w, dot);
    }
    float s = __fadd_rn(__fsub_rn(rs, __fmul_rn(2.0f, dot)), cs);
    return make_key(s, code);
}

__global__ void __launch_bounds__(CTA)
rvq_kernel(const float* __restrict__ x,
           const float* __restrict__ cb,
           float* __restrict__ out) {
    extern __shared__ float sm[];
    float* tile = sm;                        // [TILE][ROWF] tf32 values
    float* scq  = sm + TILE * ROWF;          // [TILE]
    float* myr_ = scq + TILE;                // [WARPS][TPW][ROWF]

    const int tid  = threadIdx.x;
    const int wid  = tid >> 5;
    const int lane = tid & 31;
    const int g    = lane >> 2;              // code row group 0..7
    const int t    = lane & 3;
    const int tokenBase = blockIdx.x * (WARPS * TPW) + wid * TPW;

    float* myr = myr_ + wid * TPW * ROWF;
    const u32 tile_b = smem_u32(tile);

    // init: lane tok<16 owns token tok; residual=x, exact rsq
    float rs = 0.f;
    if (lane < TPW) {
        const float4* xr = reinterpret_cast<const float4*>(
            x + (size_t)(tokenBase + lane) * DIM);
        float* mrow = myr + lane * ROWF;
#pragma unroll
        for (int i = 0; i < DIM / 4; i++) {
            float4 v = xr[i];
            mrow[4 * i]     = v.x;  rs = __fadd_rn(rs, __fmul_rn(v.x, v.x));
            mrow[4 * i + 1] = v.y;  rs = __fadd_rn(rs, __fmul_rn(v.y, v.y));
            mrow[4 * i + 2] = v.z;  rs = __fadd_rn(rs, __fmul_rn(v.z, v.z));
            mrow[4 * i + 3] = v.w;  rs = __fadd_rn(rs, __fmul_rn(v.w, v.w));
        }
    }
    __syncwarp();
    float rs0 = __shfl_sync(0xffffffffu, rs, g);
    float rs1 = __shfl_sync(0xffffffffu, rs, g + 8);

#pragma unroll 1
    for (int q = 0; q < NQ; q++) {
        // A fragments (residuals, tf32) for this stage
        u32 Ar[8][4];
#pragma unroll
        for (int kk = 0; kk < 8; kk++) {
            Ar[kk][0] = to_tf32(myr[g * ROWF + 8 * kk + t]);
            Ar[kk][1] = to_tf32(myr[(g + 8) * ROWF + 8 * kk + t]);
            Ar[kk][2] = to_tf32(myr[g * ROWF + 8 * kk + t + 4]);
            Ar[kk][3] = to_tf32(myr[(g + 8) * ROWF + 8 * kk + t + 4]);
        }

        const float maxcsq = __uint_as_float(g_maxcsq[q]);
        const float C9 = 1.0f / 512.0f;
        const float bmax0 = (rs0 + maxcsq) * C9;
        const float bmax1 = (rs1 + maxcsq) * C9;

        float min0 = 3.4e38f, min1 = 3.4e38f;

        // ---------------- PASS 1: approx min only (branchless) ----------------
#pragma unroll 1
        for (int c = 0; c < KCODES / TILE; c++) {
            __syncthreads();
            {
                const float* src = g_cbtf
                    + ((size_t)q * KCODES + c * TILE + tid) * DIM;
#pragma unroll
                for (int i = 0; i < DIM / 4; i++)
                    cp_async16(tile_b + (u32)((tid * ROWF + 4 * i) * 4),
                               src + 4 * i);
                scq[tid] = g_csq[q * KCODES + c * TILE + tid];
                asm volatile("cp.async.commit_group;" ::: "memory");
                asm volatile("cp.async.wait_group 0;" ::: "memory");
            }
            __syncthreads();

#pragma unroll 1
            for (int nb = 0; nb < TILE / 8; nb++) {
                float d0 = 0.f, d1 = 0.f, d2 = 0.f, d3 = 0.f;
                const float* brow = tile + (nb * 8 + g) * ROWF;
#pragma unroll
                for (int kk = 0; kk < 8; kk++) {
                    u32 b0 = __float_as_uint(brow[8 * kk + t]);
                    u32 b1 = __float_as_uint(brow[8 * kk + t + 4]);
                    mma8(d0, d1, d2, d3,
                         Ar[kk][0], Ar[kk][1], Ar[kk][2], Ar[kk][3], b0, b1);
                }
                float cs0 = scq[nb * 8 + 2 * t];
                float cs1 = scq[nb * 8 + 2 * t + 1];
                min0 = fminf(min0, fminf(fmaf(-2.f, d0, rs0) + cs0,
                                         fmaf(-2.f, d1, rs0) + cs1));
                min1 = fminf(min1, fminf(fmaf(-2.f, d2, rs1) + cs0,
                                         fmaf(-2.f, d3, rs1) + cs1));
            }
        }
        // merge approx mins across the quad (codes split over 4 lanes)
        min0 = fminf(min0, __shfl_xor_sync(0xffffffffu, min0, 1));
        min0 = fminf(min0, __shfl_xor_sync(0xffffffffu, min0, 2));
        min1 = fminf(min1, __shfl_xor_sync(0xffffffffu, min1, 1));
        min1 = fminf(min1, __shfl_xor_sync(0xffffffffu, min1, 2));
        const float th0 = min0 + bmax0;
        const float th1 = min1 + bmax1;

        // ------- PASS 2: identical MMA; collect+exact-rescore candidates -------
        u64 key0 = 0xFFFFFFFFFFFFFFFFull, key1 = 0xFFFFFFFFFFFFFFFFull;
#pragma unroll 1
        for (int c = 0; c < KCODES / TILE; c++) {
            __syncthreads();
            {
                const float* src = g_cbtf
                    + ((size_t)q * KCODES + c * TILE + tid) * DIM;
#pragma unroll
                for (int i = 0; i < DIM / 4; i++)
                    cp_async16(tile_b + (u32)((tid * ROWF + 4 * i) * 4),
                               src + 4 * i);
                scq[tid] = g_csq[q * KCODES + c * TILE + tid];
                asm volatile("cp.async.commit_group;" ::: "memory");
                asm volatile("cp.async.wait_group 0;" ::: "memory");
            }
            __syncthreads();

            const float* cbq = cb + (size_t)q * KCODES * DIM;
#pragma unroll 1
            for (int nb = 0; nb < TILE / 8; nb++) {
                float d0 = 0.f, d1 = 0.f, d2 = 0.f, d3 = 0.f;
                const float* brow = tile + (nb * 8 + g) * ROWF;
#pragma unroll
                for (int kk = 0; kk < 8; kk++) {
                    u32 b0 = __float_as_uint(brow[8 * kk + t]);
                    u32 b1 = __float_as_uint(brow[8 * kk + t + 4]);
                    mma8(d0, d1, d2, d3,
                         Ar[kk][0], Ar[kk][1], Ar[kk][2], Ar[kk][3], b0, b1);
                }
                u32 k0 = (u32)(c * TILE + nb * 8 + 2 * t);
                float cs0 = scq[nb * 8 + 2 * t];
                float cs1 = scq[nb * 8 + 2 * t + 1];

                float s00 = fmaf(-2.f, d0, rs0) + cs0;
                float s01 = fmaf(-2.f, d1, rs0) + cs1;
                float s10 = fmaf(-2.f, d2, rs1) + cs0;
                float s11 = fmaf(-2.f, d3, rs1) + cs1;

                if (s00 - (rs0 + cs0) * C9 <= th0) {
                    u64 k = rescore(cbq + (size_t)k0 * DIM,
                                    myr + g * ROWF, rs0, cs0, k0);
                    if (k < key0) key0 = k;
                }
                if (s01 - (rs0 + cs1) * C9 <= th0) {
                    u64 k = rescore(cbq + (size_t)(k0 + 1) * DIM,
                                    myr + g * ROWF, rs0, cs1, k0 + 1);
                    if (k < key0) key0 = k;
                }
                if (s10 - (rs1 + cs0) * C9 <= th1) {
                    u64 k = rescore(cbq + (size_t)k0 * DIM,
                                    myr + (g + 8) * ROWF, rs1, cs0, k0);
                    if (k < key1) key1 = k;
                }
                if (s11 - (rs1 + cs1) * C9 <= th1) {
                    u64 k = rescore(cbq + (size_t)(k0 + 1) * DIM,
                                    myr + (g + 8) * ROWF, rs1, cs1, k0 + 1);
                    if (k < key1) key1 = k;
                }
            }
        }

        // merge exact keys across the quad (first-min by construction)
        {
            u64 o;
            o = __shfl_xor_sync(0xffffffffu, key0, 1); if (o < key0) key0 = o;
            o = __shfl_xor_sync(0xffffffffu, key0, 2); if (o < key0) key0 = o;
            o = __shfl_xor_sync(0xffffffffu, key1, 1); if (o < key1) key1 = o;
            o = __shfl_xor_sync(0xffffffffu, key1, 2); if (o < key1) key1 = o;
        }

        // route winner to owner lane (token tok owned by lane tok)
        int src = (lane & 7) * 4;
        u64 kw0 = __shfl_sync(0xffffffffu, key0, src);
        u64 kw1 = __shfl_sync(0xffffffffu, key1, src);
        u64 kw  = (lane < 8) ? kw0 : kw1;

        // residual update + fused exact next-stage rsq
        rs = 0.f;
        if (lane < TPW) {
            float* mrow = myr + lane * ROWF;
            u32 bk = (u32)(kw & 0xFFFFull);
            const float4* crow = reinterpret_cast<const float4*>(
                cb + ((size_t)q * KCODES + bk) * DIM);
#pragma unroll
            for (int i = 0; i < DIM / 4; i++) {
                float4 v = crow[i];
                float r0 = __fsub_rn(mrow[4 * i],     v.x);
                float r1 = __fsub_rn(mrow[4 * i + 1], v.y);
                float r2 = __fsub_rn(mrow[4 * i + 2], v.z);
                float r3 = __fsub_rn(mrow[4 * i + 3], v.w);
                mrow[4 * i]     = r0;
                mrow[4 * i + 1] = r1;
                mrow[4 * i + 2] = r2;
                mrow[4 * i + 3] = r3;
                rs = __fadd_rn(rs, __fmul_rn(r0, r0));
                rs = __fadd_rn(rs, __fmul_rn(r1, r1));
                rs = __fadd_rn(rs, __fmul_rn(r2, r2));
                rs = __fadd_rn(rs, __fmul_rn(r3, r3));
            }
        }
        __syncwarp();
        rs0 = __shfl_sync(0xffffffffu, rs, g);
        rs1 = __shfl_sync(0xffffffffu, rs, g + 8);
    }

    // out = x - residual_final (exact fsub)
    if (lane < TPW) {
        const float4* xr = reinterpret_cast<const float4*>(
            x + (size_t)(tokenBase + lane) * DIM);
        float4* orw = reinterpret_cast<float4*>(
            out + (size_t)(tokenBase + lane) * DIM);
        const float* mrow = myr + lane * ROWF;
#pragma unroll
        for (int i = 0; i < DIM / 4; i++) {
            float4 v = xr[i];
            v.x = __fsub_rn(v.x, mrow[4 * i]);
            v.y = __fsub_rn(v.y, mrow[4 * i + 1]);
            v.z = __fsub_rn(v.z, mrow[4 * i + 2]);
            v.w = __fsub_rn(v.w, mrow[4 * i + 3]);
            orw[i] = v;
        }
    }
}

extern "C" void kernel_launch(void* const* d_in, const int* in_sizes, int n_in,
                              void* d_out, int out_size) {
    const float* x;
    const float* cb;
    if (in_sizes[0] == NQ * KCODES * DIM) {
        cb = (const float*)d_in[0];
        x  = (const float*)d_in[1];
    } else {
        x  = (const float*)d_in[0];
        cb = (const float*)d_in[1];
    }
    float* out = (float*)d_out;

    const int smem_bytes = (TILE * ROWF + TILE + WARPS * TPW * ROWF)
                           * (int)sizeof(float);
    cudaFuncSetAttribute(rvq_kernel,
                         cudaFuncAttributeMaxDynamicSharedMemorySize, smem_bytes);

    prep_kernel<<<(NQ * KCODES) / 128, 128>>>(cb);
    rvq_kernel<<<TOKENS / (WARPS * TPW), CTA, smem_bytes>>>(x, cb, out);
}

// round 15
// speedup vs baseline: 10.7215x; 1.0949x over previous
#include <cuda_runtime.h>

#define NQ      8
#define KCODES  1024
#define DIM     64
#define TOKENS  65536
#define TILE    128
#define CTA     256
#define WARPS   8
#define TPW     16
#define ROWF    68
#define TILEF   (TILE * ROWF)
#define NSTEP   (NQ * 16)          // 8 stages x 2 passes x 8 tiles

typedef unsigned long long u64;
typedef unsigned int u32;

__device__ float g_csq[NQ * KCODES];
__device__ u32   g_maxcsq[NQ];
__device__ float g_cbtf[NQ * KCODES * DIM];   // tf32, fragment-permuted rows

__device__ __forceinline__ u64 make_key(float s, u32 idx) {
    u32 b = __float_as_uint(s);
    u32 u = b ^ (u32)(((int)b >> 31) | 0x80000000);
    return ((u64)u << 32) | idx;
}
__device__ __forceinline__ u32 to_tf32(float f) {
    u32 r;
    asm("cvt.rna.tf32.f32 %0, %1;" : "=r"(r) : "f"(f));
    return r;
}
__device__ __forceinline__ u32 smem_u32(const void* p) {
    u32 a;
    asm("{ .reg .u64 t; cvta.to.shared.u64 t, %1; cvt.u32.u64 %0, t; }"
        : "=r"(a) : "l"(p));
    return a;
}
__device__ __forceinline__ void cp_async16(u32 dst, const void* src) {
    asm volatile("cp.async.cg.shared.global [%0], [%1], 16;"
                 :: "r"(dst), "l"(src) : "memory");
}
__device__ __forceinline__ void mma8(float& d0, float& d1, float& d2, float& d3,
                                     u32 a0, u32 a1, u32 a2, u32 a3,
                                     u32 b0, u32 b1) {
    asm("mma.sync.aligned.m16n8k8.row.col.f32.tf32.tf32.f32 "
        "{%0,%1,%2,%3},{%4,%5,%6,%7},{%8,%9},{%0,%1,%2,%3};"
        : "+f"(d0), "+f"(d1), "+f"(d2), "+f"(d3)
        : "r"(a0), "r"(a1), "r"(a2), "r"(a3), "r"(b0), "r"(b1));
}

// prep: exact csq, per-stage max, tf32 codebook in fragment order
// permuted index: p(d) = (d & 3) * 16 + (d >> 2)
__global__ void prep_kernel(const float* __restrict__ cb) {
    int r = blockIdx.x * blockDim.x + threadIdx.x;    // 0..8191
    const float* row = cb + (size_t)r * DIM;
    float s = 0.f;
#pragma unroll
    for (int d = 0; d < DIM; d++)
        s = __fadd_rn(s, __fmul_rn(row[d], row[d]));
    g_csq[r] = s;
    atomicMax(&g_maxcsq[r >> 10], __float_as_uint(s));
#pragma unroll
    for (int d = 0; d < DIM; d++)
        g_cbtf[r * DIM + (d & 3) * 16 + (d >> 2)]
            = __uint_as_float(to_tf32(row[d]));
}

// exact rescore: sequential d-ascending fp32 fma chain (reference recipe)
__device__ __forceinline__ u64 rescore(const float* __restrict__ crow,
                                       const float* __restrict__ mrow,
                                       float rs, float cs, u32 code) {
    float dot = 0.f;
#pragma unroll 1
    for (int i = 0; i < DIM / 4; i++) {
        float4 cv = reinterpret_cast<const float4*>(crow)[i];
        float4 rv = reinterpret_cast<const float4*>(mrow)[i];
        dot = __fmaf_rn(rv.x, cv.x, dot);
        dot = __fmaf_rn(rv.y, cv.y, dot);
        dot = __fmaf_rn(rv.z, cv.z, dot);
        dot = __fmaf_rn(rv.w, cv.w, dot);
    }
    float s = __fadd_rn(__fsub_rn(rs, __fmul_rn(2.0f, dot)), cs);
    return make_key(s, code);
}

__global__ void __launch_bounds__(CTA)
rvq_kernel(const float* __restrict__ x,
           const float* __restrict__ cb,
           float* __restrict__ out) {
    extern __shared__ float sm[];
    float* tileB = sm;                       // [2][TILEF]
    float* scqB  = sm + 2 * TILEF;           // [2][TILE]
    float* myr_  = scqB + 2 * TILE;          // [WARPS][TPW][ROWF]

    const int tid  = threadIdx.x;
    const int wid  = tid >> 5;
    const int lane = tid & 31;
    const int g    = lane >> 2;
    const int t    = lane & 3;
    const int tokenBase = blockIdx.x * (WARPS * TPW) + wid * TPW;

    float* myr = myr_ + wid * TPW * ROWF;
    const u32 tile_b = smem_u32(tileB);

    // init: lane tok<16 owns token tok; residual=x, exact rsq
    float rs = 0.f;
    if (lane < TPW) {
        const float4* xr = reinterpret_cast<const float4*>(
            x + (size_t)(tokenBase + lane) * DIM);
        float* mrow = myr + lane * ROWF;
#pragma unroll
        for (int i = 0; i < DIM / 4; i++) {
            float4 v = xr[i];
            mrow[4 * i]     = v.x;  rs = __fadd_rn(rs, __fmul_rn(v.x, v.x));
            mrow[4 * i + 1] = v.y;  rs = __fadd_rn(rs, __fmul_rn(v.y, v.y));
            mrow[4 * i + 2] = v.z;  rs = __fadd_rn(rs, __fmul_rn(v.z, v.z));
            mrow[4 * i + 3] = v.w;  rs = __fadd_rn(rs, __fmul_rn(v.w, v.w));
        }
    }
    __syncwarp();
    float rs0 = __shfl_sync(0xffffffffu, rs, g);
    float rs1 = __shfl_sync(0xffffffffu, rs, g + 8);

    // prefetch step 0 tile (row = tid>>1, half-row = tid&1) + its csq
    {
        const int row = tid >> 1, half = tid & 1;
        const float* src = g_cbtf + (size_t)row * DIM + half * 32;
        u32 dst = tile_b + (u32)((row * ROWF + half * 32) * 4);
#pragma unroll
        for (int i = 0; i < 8; i++)
            cp_async16(dst + 16u * i, src + 4 * i);
        asm volatile("cp.async.commit_group;" ::: "memory");
        if (tid < TILE) scqB[tid] = g_csq[tid];
    }

    // persistent per-stage state
    u32 Ar[8][4];
    float bmax0 = 0.f, bmax1 = 0.f, min0 = 0.f, min1 = 0.f;
    float th0 = 0.f, th1 = 0.f;
    u64 key0 = 0, key1 = 0;
    const float C9 = 1.0f / 512.0f;

#pragma unroll 1
    for (int s = 0; s < NSTEP; s++) {
        const int q    = s >> 4;
        const int pass = (s >> 3) & 1;
        const int c    = s & 7;

        asm volatile("cp.async.wait_group 0;" ::: "memory");
        __syncthreads();

        // prefetch step s+1 into the other buffer (overlaps compute)
        if (s + 1 < NSTEP) {
            const int s2 = s + 1;
            const int q2 = s2 >> 4, c2 = s2 & 7;
            const int row = tid >> 1, half = tid & 1;
            const float* src = g_cbtf
                + ((size_t)q2 * KCODES + c2 * TILE + row) * DIM + half * 32;
            u32 dst = tile_b + (u32)(s2 & 1) * (TILEF * 4)
                    + (u32)((row * ROWF + half * 32) * 4);
#pragma unroll
            for (int i = 0; i < 8; i++)
                cp_async16(dst + 16u * i, src + 4 * i);
            asm volatile("cp.async.commit_group;" ::: "memory");
            if (tid < TILE)
                scqB[(s2 & 1) * TILE + tid]
                    = g_csq[q2 * KCODES + c2 * TILE + tid];
        }

        const float* tile = tileB + (s & 1) * TILEF;
        const float* scq  = scqB  + (s & 1) * TILE;

        if (pass == 0 && c == 0) {
            // stage init: A fragments (tf32) + bounds + min reset
#pragma unroll
            for (int kk = 0; kk < 8; kk++) {
                Ar[kk][0] = to_tf32(myr[g * ROWF + 8 * kk + t]);
                Ar[kk][1] = to_tf32(myr[(g + 8) * ROWF + 8 * kk + t]);
                Ar[kk][2] = to_tf32(myr[g * ROWF + 8 * kk + t + 4]);
                Ar[kk][3] = to_tf32(myr[(g + 8) * ROWF + 8 * kk + t + 4]);
            }
            const float maxcsq = __uint_as_float(g_maxcsq[q]);
            bmax0 = (rs0 + maxcsq) * C9;
            bmax1 = (rs1 + maxcsq) * C9;
            min0 = 3.4e38f;
            min1 = 3.4e38f;
        }
        if (pass == 1 && c == 0) {
            // pass-1 done: merge mins across quad, set thresholds, reset keys
            min0 = fminf(min0, __shfl_xor_sync(0xffffffffu, min0, 1));
            min0 = fminf(min0, __shfl_xor_sync(0xffffffffu, min0, 2));
            min1 = fminf(min1, __shfl_xor_sync(0xffffffffu, min1, 1));
            min1 = fminf(min1, __shfl_xor_sync(0xffffffffu, min1, 2));
            th0 = min0 + bmax0;
            th1 = min1 + bmax1;
            key0 = 0xFFFFFFFFFFFFFFFFull;
            key1 = 0xFFFFFFFFFFFFFFFFull;
        }

        const float* cbq = cb + (size_t)q * KCODES * DIM;

#pragma unroll 2
        for (int nb = 0; nb < TILE / 8; nb++) {
            float d0 = 0.f, d1 = 0.f, d2 = 0.f, d3 = 0.f;
            // B fragments: 4x LDS.128, fragment-permuted layout
            const float4* brow4 = reinterpret_cast<const float4*>(
                tile + (nb * 8 + g) * ROWF) + t * 4;
            float4 f0 = brow4[0], f1 = brow4[1], f2 = brow4[2], f3 = brow4[3];
            mma8(d0, d1, d2, d3, Ar[0][0], Ar[0][1], Ar[0][2], Ar[0][3],
                 __float_as_uint(f0.x), __float_as_uint(f0.y));
            mma8(d0, d1, d2, d3, Ar[1][0], Ar[1][1], Ar[1][2], Ar[1][3],
                 __float_as_uint(f0.z), __float_as_uint(f0.w));
            mma8(d0, d1, d2, d3, Ar[2][0], Ar[2][1], Ar[2][2], Ar[2][3],
                 __float_as_uint(f1.x), __float_as_uint(f1.y));
            mma8(d0, d1, d2, d3, Ar[3][0], Ar[3][1], Ar[3][2], Ar[3][3],
                 __float_as_uint(f1.z), __float_as_uint(f1.w));
            mma8(d0, d1, d2, d3, Ar[4][0], Ar[4][1], Ar[4][2], Ar[4][3],
                 __float_as_uint(f2.x), __float_as_uint(f2.y));
            mma8(d0, d1, d2, d3, Ar[5][0], Ar[5][1], Ar[5][2], Ar[5][3],
                 __float_as_uint(f2.z), __float_as_uint(f2.w));
            mma8(d0, d1, d2, d3, Ar[6][0], Ar[6][1], Ar[6][2], Ar[6][3],
                 __float_as_uint(f3.x), __float_as_uint(f3.y));
            mma8(d0, d1, d2, d3, Ar[7][0], Ar[7][1], Ar[7][2], Ar[7][3],
                 __float_as_uint(f3.z), __float_as_uint(f3.w));

            float cs0 = scq[nb * 8 + 2 * t];
            float cs1 = scq[nb * 8 + 2 * t + 1];
            float s00 = fmaf(-2.f, d0, rs0) + cs0;
            float s01 = fmaf(-2.f, d1, rs0) + cs1;
            float s10 = fmaf(-2.f, d2, rs1) + cs0;
            float s11 = fmaf(-2.f, d3, rs1) + cs1;

            if (pass == 0) {
                min0 = fminf(min0, fminf(s00, s01));
                min1 = fminf(min1, fminf(s10, s11));
            } else {
                u32 k0 = (u32)(c * TILE + nb * 8 + 2 * t);
                if (s00 - (rs0 + cs0) * C9 <= th0) {
                    u64 k = rescore(cbq + (size_t)k0 * DIM,
                                    myr + g * ROWF, rs0, cs0, k0);
                    if (k < key0) key0 = k;
                }
                if (s01 - (rs0 + cs1) * C9 <= th0) {
                    u64 k = rescore(cbq + (size_t)(k0 + 1) * DIM,
                                    myr + g * ROWF, rs0, cs1, k0 + 1);
                    if (k < key0) key0 = k;
                }
                if (s10 - (rs1 + cs0) * C9 <= th1) {
                    u64 k = rescore(cbq + (size_t)k0 * DIM,
                                    myr + (g + 8) * ROWF, rs1, cs0, k0);
                    if (k < key1) key1 = k;
                }
                if (s11 - (rs1 + cs1) * C9 <= th1) {
                    u64 k = rescore(cbq + (size_t)(k0 + 1) * DIM,
                                    myr + (g + 8) * ROWF, rs1, cs1, k0 + 1);
                    if (k < key1) key1 = k;
                }
            }
        }

        if (pass == 1 && c == 7) {
            // stage end: merge exact keys (first-min), update residuals
            u64 o;
            o = __shfl_xor_sync(0xffffffffu, key0, 1); if (o < key0) key0 = o;
            o = __shfl_xor_sync(0xffffffffu, key0, 2); if (o < key0) key0 = o;
            o = __shfl_xor_sync(0xffffffffu, key1, 1); if (o < key1) key1 = o;
            o = __shfl_xor_sync(0xffffffffu, key1, 2); if (o < key1) key1 = o;

            int srcl = (lane & 7) * 4;
            u64 kw0 = __shfl_sync(0xffffffffu, key0, srcl);
            u64 kw1 = __shfl_sync(0xffffffffu, key1, srcl);
            u64 kw  = (lane < 8) ? kw0 : kw1;

            rs = 0.f;
            if (lane < TPW) {
                float* mrow = myr + lane * ROWF;
                u32 bk = (u32)(kw & 0xFFFFull);
                const float4* crow = reinterpret_cast<const float4*>(
                    cb + ((size_t)q * KCODES + bk) * DIM);
#pragma unroll
                for (int i = 0; i < DIM / 4; i++) {
                    float4 v = crow[i];
                    float r0 = __fsub_rn(mrow[4 * i],     v.x);
                    float r1 = __fsub_rn(mrow[4 * i + 1], v.y);
                    float r2 = __fsub_rn(mrow[4 * i + 2], v.z);
                    float r3 = __fsub_rn(mrow[4 * i + 3], v.w);
                    mrow[4 * i]     = r0;
                    mrow[4 * i + 1] = r1;
                    mrow[4 * i + 2] = r2;
                    mrow[4 * i + 3] = r3;
                    rs = __fadd_rn(rs, __fmul_rn(r0, r0));
                    rs = __fadd_rn(rs, __fmul_rn(r1, r1));
                    rs = __fadd_rn(rs, __fmul_rn(r2, r2));
                    rs = __fadd_rn(rs, __fmul_rn(r3, r3));
                }
            }
            __syncwarp();
            rs0 = __shfl_sync(0xffffffffu, rs, g);
            rs1 = __shfl_sync(0xffffffffu, rs, g + 8);
        }
    }

    // out = x - residual_final (exact fsub)
    if (lane < TPW) {
        const float4* xr = reinterpret_cast<const float4*>(
            x + (size_t)(tokenBase + lane) * DIM);
        float4* orw = reinterpret_cast<float4*>(
            out + (size_t)(tokenBase + lane) * DIM);
        const float* mrow = myr + lane * ROWF;
#pragma unroll
        for (int i = 0; i < DIM / 4; i++) {
            float4 v = xr[i];
            v.x = __fsub_rn(v.x, mrow[4 * i]);
            v.y = __fsub_rn(v.y, mrow[4 * i + 1]);
            v.z = __fsub_rn(v.z, mrow[4 * i + 2]);
            v.w = __fsub_rn(v.w, mrow[4 * i + 3]);
            orw[i] = v;
        }
    }
}

extern "C" void kernel_launch(void* const* d_in, const int* in_sizes, int n_in,
                              void* d_out, int out_size) {
    const float* x;
    const float* cb;
    if (in_sizes[0] == NQ * KCODES * DIM) {
        cb = (const float*)d_in[0];
        x  = (const float*)d_in[1];
    } else {
        x  = (const float*)d_in[0];
        cb = (const float*)d_in[1];
    }
    float* out = (float*)d_out;

    const int smem_bytes = (2 * TILEF + 2 * TILE + WARPS * TPW * ROWF)
                           * (int)sizeof(float);
    cudaFuncSetAttribute(rvq_kernel,
                         cudaFuncAttributeMaxDynamicSharedMemorySize, smem_bytes);

    prep_kernel<<<(NQ * KCODES) / 128, 128>>>(cb);
    rvq_kernel<<<TOKENS / (WARPS * TPW), CTA, smem_bytes>>>(x, cb, out);
}